// round 6
// baseline (speedup 1.0000x reference)
#include <cuda_runtime.h>

// DDK_77644418777653 — per-row recurrence scan, transposed-tile SMEM staging.
//
// out[:,0] = 1 ; out[:,k] = out[:,k-1] + alpha/out[:,k-1] - beta*in[:,k-1]
// M = 262144 rows, N = 512 cols, fp32, row-major.
//
// Each block owns 256 rows (one thread per row). Columns processed in 16
// aligned tiles of 32. Cooperative float4 gmem <-> smem staging keeps all
// global traffic coalesced (exactly 512 MB read + 512 MB write). The input
// value consumed by the first column of a tile is carried in a register
// (xprev) from the previous tile, so tiles stay 128B-aligned on both ends.
//
// fp semantics match XLA:GPU's lowering exactly (required: the recurrence is
// chaotic, 1 ulp diverges to O(1) on rows where w -> 0):
//   t  = div.rn(a, w)          (XLA fdiv -> div.rn.f32, IEEE)
//   u  = add.rn(w, t)
//   w' = ffma.rn(-b, x, u)     (XLA NVPTX AllowFPOpFusion::Fast contracts
//                               fsub(u, fmul(b,x)) into a single-rounded FMA)

#define ROWS_PER_BLOCK 256
#define TK             32
#define LDSR           33   // padded smem row stride (33 % 32 == 1 -> conflict-free)
#define NCOLS          512
#define N4             (NCOLS / 4)

__global__ __launch_bounds__(ROWS_PER_BLOCK)
void DDK_77644418777653_kernel(const float* __restrict__ in,
                               const float* __restrict__ alpha,
                               const float* __restrict__ beta,
                               float* __restrict__ out) {
    __shared__ float sm[ROWS_PER_BLOCK * LDSR];

    const int tid  = threadIdx.x;
    const int row0 = blockIdx.x * ROWS_PER_BLOCK;

    const float a = alpha[0];
    const float b = beta[0];

    const float4* in4  = reinterpret_cast<const float4*>(in);
    float4*       out4 = reinterpret_cast<float4*>(out);

    float w     = 1.0f;   // recurrence state for this thread's row
    float xprev = 0.0f;   // input value carried across tile boundary

    for (int t = 0; t < NCOLS / TK; ++t) {
        const int k0 = t * TK;

        // ---- cooperative coalesced load: in[row0:row0+256, k0:k0+32) ----
        // 256 rows * 8 float4/row = 2048 float4 slots, 8 per thread.
        #pragma unroll
        for (int it = 0; it < (ROWS_PER_BLOCK * TK / 4) / ROWS_PER_BLOCK; ++it) {
            int idx = it * ROWS_PER_BLOCK + tid;   // 0..2047
            int r   = idx >> 3;                    // smem row
            int c4  = idx & 7;                     // float4 slot in row
            float4 v = in4[(row0 + r) * N4 + (k0 >> 2) + c4];
            float* d = &sm[r * LDSR + c4 * 4];
            d[0] = v.x; d[1] = v.y; d[2] = v.z; d[3] = v.w;
        }
        __syncthreads();

        // ---- per-thread serial recurrence over this tile (in-place) ----
        bool  first = (t == 0);
        float* mrow = &sm[tid * LDSR];
        #pragma unroll
        for (int i = 0; i < TK; ++i) {
            float x = mrow[i];  // input col k0+i (read before overwrite)
            // out col (k0+i) uses input col (k0+i-1) = xprev.
            // Exact XLA:GPU op sequence: add(w, div(a,w)) then fused
            // multiply-subtract (single rounding).
            float u  = __fadd_rn(w, __fdiv_rn(a, w));
            float wn = __fmaf_rn(-b, xprev, u);
            w = first ? 1.0f : wn;   // col 0 of the whole row is exactly 1
            mrow[i] = w;
            xprev   = x;
            first   = false;         // constant-folds away for i >= 1
        }
        __syncthreads();

        // ---- cooperative coalesced store: out[row0:row0+256, k0:k0+32) ----
        #pragma unroll
        for (int it = 0; it < (ROWS_PER_BLOCK * TK / 4) / ROWS_PER_BLOCK; ++it) {
            int idx = it * ROWS_PER_BLOCK + tid;
            int r   = idx >> 3;
            int c4  = idx & 7;
            const float* s = &sm[r * LDSR + c4 * 4];
            float4 v = make_float4(s[0], s[1], s[2], s[3]);
            out4[(row0 + r) * N4 + (k0 >> 2) + c4] = v;
        }
        __syncthreads();
    }
}

extern "C" void kernel_launch(void* const* d_in, const int* in_sizes, int n_in,
                              void* d_out, int out_size) {
    const float* in    = (const float*)d_in[0];   // [262144, 512] fp32
    const float* alpha = (const float*)d_in[1];   // [1]
    const float* beta  = (const float*)d_in[2];   // [1]
    float*       out   = (float*)d_out;           // [262144, 512] fp32

    const int M = in_sizes[0] / NCOLS;            // 262144
    DDK_77644418777653_kernel<<<M / ROWS_PER_BLOCK, ROWS_PER_BLOCK>>>(
        in, alpha, beta, out);
}